// round 12
// baseline (speedup 1.0000x reference)
#include <cuda_runtime.h>
#include <math.h>
#include <stdint.h>

#define Gn 8
#define Hn 64
#define In 64
#define Bn 32
#define Tn 1000
#define XSTR (Gn * In)   // 512 floats per (b,t)
#define TILES (Tn / 8)   // 125

// Scratch: xp[(bg*T + t)*192 + j] — written by block bg's producer warps,
// read by the same block's scan warps.
__device__ float g_xp[(size_t)Bn * Gn * Tn * 192];

// ---------------- packed f32x2 helpers (sm_103a) ----------------
__device__ __forceinline__ uint64_t ffma2(uint64_t a, uint64_t b, uint64_t c) {
    uint64_t d;
    asm("fma.rn.f32x2 %0, %1, %2, %3;" : "=l"(d) : "l"(a), "l"(b), "l"(c));
    return d;
}
__device__ __forceinline__ uint64_t fadd2(uint64_t a, uint64_t b) {
    uint64_t d;
    asm("add.rn.f32x2 %0, %1, %2;" : "=l"(d) : "l"(a), "l"(b));
    return d;
}
__device__ __forceinline__ uint64_t pack2(float lo, float hi) {
    uint64_t d;
    asm("mov.b64 %0, {%1, %2};" : "=l"(d) : "f"(lo), "f"(hi));
    return d;
}
__device__ __forceinline__ float2 unpack2(uint64_t v) {
    float lo, hi;
    asm("mov.b64 {%0, %1}, %2;" : "=f"(lo), "=f"(hi) : "l"(v));
    return make_float2(lo, hi);
}
__device__ __forceinline__ float fsig(float x) {
    return __fdividef(1.f, 1.f + __expf(-x));
}

// 64-wide dot: w = 16 ulonglong2 (64 floats), v = 64 floats in smem
__device__ __forceinline__ float dot64(const ulonglong2* w, const float* v, float seed) {
    const ulonglong2* v2 = (const ulonglong2*)v;
    uint64_t a0 = pack2(seed, 0.f), a1 = 0ull, a2 = 0ull, a3 = 0ull;
#pragma unroll
    for (int q = 0; q < 16; q += 2) {
        ulonglong2 va = v2[q];
        ulonglong2 vb = v2[q + 1];
        a0 = ffma2(w[q].x,     va.x, a0);
        a1 = ffma2(w[q].y,     va.y, a1);
        a2 = ffma2(w[q + 1].x, vb.x, a2);
        a3 = ffma2(w[q + 1].y, vb.y, a3);
    }
    float2 f = unpack2(fadd2(fadd2(a0, a1), fadd2(a2, a3)));
    return f.x + f.y;
}

// Two 64-wide dots sharing one vector load
__device__ __forceinline__ float2 dot64x2(const ulonglong2* wA, const ulonglong2* wB,
                                          const float* v, float sA, float sB) {
    const ulonglong2* v2 = (const ulonglong2*)v;
    uint64_t a0 = pack2(sA, 0.f), a1 = 0ull, a2 = 0ull, a3 = 0ull;
    uint64_t b0 = pack2(sB, 0.f), b1 = 0ull, b2 = 0ull, b3 = 0ull;
#pragma unroll
    for (int q = 0; q < 16; q += 2) {
        ulonglong2 va = v2[q];
        ulonglong2 vb = v2[q + 1];
        a0 = ffma2(wA[q].x,     va.x, a0);
        a1 = ffma2(wA[q].y,     va.y, a1);
        a2 = ffma2(wA[q + 1].x, vb.x, a2);
        a3 = ffma2(wA[q + 1].y, vb.y, a3);
        b0 = ffma2(wB[q].x,     va.x, b0);
        b1 = ffma2(wB[q].y,     va.y, b1);
        b2 = ffma2(wB[q + 1].x, vb.x, b2);
        b3 = ffma2(wB[q + 1].y, vb.y, b3);
    }
    float2 fa = unpack2(fadd2(fadd2(a0, a1), fadd2(a2, a3)));
    float2 fb = unpack2(fadd2(fadd2(b0, b1), fadd2(b2, b3)));
    return make_float2(fa.x + fa.y, fb.x + fb.y);
}

#define SCAN_BAR() asm volatile("bar.sync 1, 192;" ::: "memory")
#define PROD_BAR() asm volatile("bar.sync 3, 96;"  ::: "memory")

// ---------------------------------------------------------------------------
// One block per (b,g); 288 threads.
//  Threads 0..191:  R2 scan (named barriers, count 192)
//  Threads 192..287: xproj producer (2 Wih rows each; own bar, count 96)
// Decoupling: smem prod_cnt (tiles of 8 steps complete), forward-only.
// grid = 256, 2 blocks/SM.
// ---------------------------------------------------------------------------
__global__ void __launch_bounds__(288, 2) gru_kernel(
    const float* __restrict__ x,
    const float* __restrict__ h0,
    const float* __restrict__ Wih,
    const float* __restrict__ Whh,
    const float* __restrict__ bih,
    const float* __restrict__ bhh,
    float* __restrict__ out)
{
    const int bg = blockIdx.x;
    const int b  = bg >> 3;
    const int g  = bg & 7;
    const int tid = threadIdx.x;

    __shared__ __align__(16) float xt[2][8][64];   // producer x tiles
    __shared__ __align__(16) float h_sh[64];
    __shared__ __align__(16) float gh_sh[192];
    __shared__ __align__(16) float xq_sh[192];
    __shared__ int prod_cnt;

    if (tid == 0) *(volatile int*)&prod_cnt = 0;
    __syncthreads();   // once, whole block — init visibility

    const float* xsrc = x + ((size_t)b * Tn) * XSTR + g * In;
    float* xp = g_xp + (size_t)bg * Tn * 192;

    if (tid >= 192) {
        // ======================= PRODUCER =======================
        const int pj = tid - 192;   // 0..95; owns Wih rows pj and pj+96
        ulonglong2 wA[16], wB[16];
        {
            const ulonglong2* pA = (const ulonglong2*)&Wih[((size_t)g * 192 + pj) * In];
            const ulonglong2* pB = (const ulonglong2*)&Wih[((size_t)g * 192 + pj + 96) * In];
#pragma unroll
            for (int q = 0; q < 16; q++) { wA[q] = pA[q]; wB[q] = pB[q]; }
        }
        const float bA = bih[g * 192 + pj];
        const float bB = bih[g * 192 + pj + 96];

        const bool ldr = (pj < 32);   // 32 loader threads, 4 float4 each
        int tt[4], qq[4];
        if (ldr) {
#pragma unroll
            for (int u = 0; u < 4; u++) {
                int idx = pj * 4 + u;
                tt[u] = idx >> 4;
                qq[u] = (idx & 15) * 4;
            }
            // stage tile 0
#pragma unroll
            for (int u = 0; u < 4; u++) {
                float4 v = *(const float4*)&xsrc[(size_t)tt[u] * XSTR + qq[u]];
                *(float4*)&xt[0][tt[u]][qq[u]] = v;
            }
        }
        PROD_BAR();

        for (int p = 0; p < TILES; p++) {
            const int buf = p & 1;
            float4 pf[4];
            const bool more = (p + 1 < TILES);
            if (more && ldr) {
#pragma unroll
                for (int u = 0; u < 4; u++)
                    pf[u] = *(const float4*)&xsrc[((size_t)(p + 1) * 8 + tt[u]) * XSTR + qq[u]];
            }
#pragma unroll
            for (int u = 0; u < 8; u++) {
                float2 d = dot64x2(wA, wB, xt[buf][u], bA, bB);
                size_t o = (size_t)(p * 8 + u) * 192;
                xp[o + pj]      = d.x;
                xp[o + pj + 96] = d.y;
            }
            if (more && ldr) {
#pragma unroll
                for (int u = 0; u < 4; u++)
                    *(float4*)&xt[buf ^ 1][tt[u]][qq[u]] = pf[u];
            }
            PROD_BAR();   // membar.cta semantics: orders STGs + xt stores
            if (pj == 0) *(volatile int*)&prod_cnt = p + 1;
        }
        return;   // producers retire
    }

    // ========================= SCAN (R2) =========================
    const int j = tid;

    ulonglong2 w[16];
    {
        const ulonglong2* wrow = (const ulonglong2*)&Whh[((size_t)g * 192 + j) * Hn];
#pragma unroll
        for (int q = 0; q < 16; q++) w[q] = wrow[q];
    }
    const float bj = bhh[g * 192 + j];

    if (j < 64) h_sh[j] = h0[((size_t)g * Bn + b) * Hn + j];

    const float* xp_col = xp + j;
    float* out_row = out + (size_t)b * Tn * (Gn * Hn) + g * Hn;
    volatile int* pc = (volatile int*)&prod_cnt;

    // wait for tile 0, then prolog prefetch (slots 0..3)
    while (*pc < 1) {}
    __threadfence_block();
    float p0 = xp_col[0];
    float p1 = xp_col[192];
    float p2 = xp_col[2 * 192];
    float p3 = xp_col[3 * 192];

#define STEP(T_, XV_)                                                         \
    {                                                                         \
        SCAN_BAR();   /* h_sh ready */                                        \
        uint64_t A0 = pack2(bj, 0.f), A1 = 0ull, A2 = 0ull, A3 = 0ull;        \
        const ulonglong2* h2 = (const ulonglong2*)h_sh;                       \
        _Pragma("unroll")                                                     \
        for (int q = 0; q < 16; q += 2) {                                     \
            ulonglong2 ha = h2[q];                                            \
            ulonglong2 hb = h2[q + 1];                                        \
            A0 = ffma2(w[q].x,     ha.x, A0);                                 \
            A1 = ffma2(w[q].y,     ha.y, A1);                                 \
            A2 = ffma2(w[q + 1].x, hb.x, A2);                                 \
            A3 = ffma2(w[q + 1].y, hb.y, A3);                                 \
        }                                                                     \
        float2 s_ = unpack2(fadd2(fadd2(A0, A1), fadd2(A2, A3)));             \
        gh_sh[j] = s_.x + s_.y;                                               \
        xq_sh[j] = XV_;                                                       \
        SCAN_BAR();   /* gh/xq ready */                                       \
        if (j < 64) {                                                         \
            float hprev = h_sh[j];                                            \
            float rr = fsig(xq_sh[j]      + gh_sh[j]);                        \
            float zz = fsig(xq_sh[64 + j] + gh_sh[64 + j]);                   \
            float aa = xq_sh[128 + j] + rr * gh_sh[128 + j];                  \
            float nn = __fmaf_rn(2.f, fsig(2.f * aa), -1.f);                  \
            float hn = nn + zz * (hprev - nn);                                \
            h_sh[j] = hn;                                                     \
            __stcs(&out_row[(size_t)(T_) * (Gn * Hn) + j], hn);               \
        }                                                                     \
    }

    for (int c = 0; c < TILES; c++) {
        // need tiles 0..c+1 complete (refills below reach slot 8c+11)
        const int need = (c + 2 < TILES) ? (c + 2) : TILES;
        while (*pc < need) {}
        __threadfence_block();

        const int t = c * 8;
        STEP(t + 0, p0);
        { int tp = min(t + 4, Tn - 1);  p0 = xp_col[(size_t)tp * 192]; }
        STEP(t + 1, p1);
        { int tp = min(t + 5, Tn - 1);  p1 = xp_col[(size_t)tp * 192]; }
        STEP(t + 2, p2);
        { int tp = min(t + 6, Tn - 1);  p2 = xp_col[(size_t)tp * 192]; }
        STEP(t + 3, p3);
        { int tp = min(t + 7, Tn - 1);  p3 = xp_col[(size_t)tp * 192]; }
        STEP(t + 4, p0);
        { int tp = min(t + 8, Tn - 1);  p0 = xp_col[(size_t)tp * 192]; }
        STEP(t + 5, p1);
        { int tp = min(t + 9, Tn - 1);  p1 = xp_col[(size_t)tp * 192]; }
        STEP(t + 6, p2);
        { int tp = min(t + 10, Tn - 1); p2 = xp_col[(size_t)tp * 192]; }
        STEP(t + 7, p3);
        { int tp = min(t + 11, Tn - 1); p3 = xp_col[(size_t)tp * 192]; }
    }
#undef STEP

    SCAN_BAR();
    if (j < 64) {
        out[(size_t)Bn * Tn * (Gn * Hn) + ((size_t)g * Bn + b) * Hn + j] = h_sh[j];
    }
}

// ---------------------------------------------------------------------------
extern "C" void kernel_launch(void* const* d_in, const int* in_sizes, int n_in,
                              void* d_out, int out_size)
{
    const float* x   = (const float*)d_in[0];
    const float* h0  = (const float*)d_in[1];
    const float* Wih = (const float*)d_in[2];
    const float* Whh = (const float*)d_in[3];
    const float* bih = (const float*)d_in[4];
    const float* bhh = (const float*)d_in[5];
    float* out = (float*)d_out;

    gru_kernel<<<Bn * Gn, 288>>>(x, h0, Wih, Whh, bih, bhh, out);
}

// round 13
// speedup vs baseline: 1.8493x; 1.8493x over previous
#include <cuda_runtime.h>
#include <math.h>
#include <stdint.h>

#define Gn 8
#define Hn 64
#define In 64
#define Bn 32
#define Tn 1000
#define XSTR (Gn * In)   // 512 floats per (b,t)
#define RS 16            // xq ring slots (steps)

// ---------------- packed f32x2 helpers (sm_103a) ----------------
__device__ __forceinline__ uint64_t ffma2(uint64_t a, uint64_t b, uint64_t c) {
    uint64_t d;
    asm("fma.rn.f32x2 %0, %1, %2, %3;" : "=l"(d) : "l"(a), "l"(b), "l"(c));
    return d;
}
__device__ __forceinline__ uint64_t fadd2(uint64_t a, uint64_t b) {
    uint64_t d;
    asm("add.rn.f32x2 %0, %1, %2;" : "=l"(d) : "l"(a), "l"(b));
    return d;
}
__device__ __forceinline__ uint64_t pack2(float lo, float hi) {
    uint64_t d;
    asm("mov.b64 %0, {%1, %2};" : "=l"(d) : "f"(lo), "f"(hi));
    return d;
}
__device__ __forceinline__ float2 unpack2(uint64_t v) {
    float lo, hi;
    asm("mov.b64 {%0, %1}, %2;" : "=f"(lo), "=f"(hi) : "l"(v));
    return make_float2(lo, hi);
}
__device__ __forceinline__ float fsig(float x) {
    return __fdividef(1.f, 1.f + __expf(-x));
}

// Three 64-wide dots (rows r,z,n) sharing ONE broadcast vector read.
// wr/wz/wn: 16 ulonglong2 each (64 floats). 96 ffma2 total, 6 chains.
__device__ __forceinline__ float3 dot64x3(const ulonglong2* wr, const ulonglong2* wz,
                                          const ulonglong2* wn, const float* v,
                                          float sr, float sz, float sn) {
    const ulonglong2* v2 = (const ulonglong2*)v;
    uint64_t r0 = pack2(sr, 0.f), r1 = 0ull;
    uint64_t z0 = pack2(sz, 0.f), z1 = 0ull;
    uint64_t n0 = pack2(sn, 0.f), n1 = 0ull;
#pragma unroll
    for (int q = 0; q < 16; q++) {
        ulonglong2 hv = v2[q];
        r0 = ffma2(wr[q].x, hv.x, r0);
        r1 = ffma2(wr[q].y, hv.y, r1);
        z0 = ffma2(wz[q].x, hv.x, z0);
        z1 = ffma2(wz[q].y, hv.y, z1);
        n0 = ffma2(wn[q].x, hv.x, n0);
        n1 = ffma2(wn[q].y, hv.y, n1);
    }
    float2 fr = unpack2(fadd2(r0, r1));
    float2 fz = unpack2(fadd2(z0, z1));
    float2 fn = unpack2(fadd2(n0, n1));
    return make_float3(fr.x + fr.y, fz.x + fz.y, fn.x + fn.y);
}

#define SCAN_BAR() asm volatile("bar.sync 1, 64;" ::: "memory")
#define PROD_BAR() asm volatile("bar.sync 2, 64;" ::: "memory")

// ---------------------------------------------------------------------------
// One block per (b,g); 128 threads.
//  Threads 0..63   (warps 0-1): scan. Thread e owns Whh rows {e, 64+e, 128+e};
//     gates computed locally; h double-buffered in smem; 1 named bar/step.
//  Threads 64..127 (warps 2-3): producer. Thread e owns Wih rows {e,64+e,128+e};
//     writes xp into a 16-step smem ring; volatile counters decouple.
// grid = 256, 2 blocks/SM.
// ---------------------------------------------------------------------------
__global__ void __launch_bounds__(128, 2) gru_kernel(
    const float* __restrict__ x,
    const float* __restrict__ h0,
    const float* __restrict__ Wih,
    const float* __restrict__ Whh,
    const float* __restrict__ bih,
    const float* __restrict__ bhh,
    float* __restrict__ out)
{
    const int bg  = blockIdx.x;
    const int b   = bg >> 3;
    const int g   = bg & 7;
    const int tid = threadIdx.x;

    __shared__ __align__(16) float xq[RS][192];   // xp ring (producer -> scan)
    __shared__ __align__(16) float xs[4][64];     // staged x rows (producer)
    __shared__ __align__(16) float hbuf[2][64];   // double-buffered h
    __shared__ int prod_steps;                    // producer progress (steps)
    __shared__ int cons_steps;                    // consumer progress (steps)

    if (tid == 0) { prod_steps = 0; cons_steps = 0; }
    __syncthreads();

    volatile int* vprod = (volatile int*)&prod_steps;
    volatile int* vcons = (volatile int*)&cons_steps;

    if (tid >= 64) {
        // ============================ PRODUCER ============================
        const int e = tid - 64;   // 0..63
        ulonglong2 wr[16], wz[16], wn[16];
        {
            const ulonglong2* p;
            p = (const ulonglong2*)&Wih[((size_t)g * 192 + e) * In];
#pragma unroll
            for (int q = 0; q < 16; q++) wr[q] = p[q];
            p = (const ulonglong2*)&Wih[((size_t)g * 192 + 64 + e) * In];
#pragma unroll
            for (int q = 0; q < 16; q++) wz[q] = p[q];
            p = (const ulonglong2*)&Wih[((size_t)g * 192 + 128 + e) * In];
#pragma unroll
            for (int q = 0; q < 16; q++) wn[q] = p[q];
        }
        const float br = bih[g * 192 + e];
        const float bz = bih[g * 192 + 64 + e];
        const float bn = bih[g * 192 + 128 + e];

        const float* xsrc = x + ((size_t)b * Tn) * XSTR + g * In;

        for (int p = 0; p < Tn / 4; p++) {
            // backpressure: writing steps 4p..4p+3 overwrites slots of steps
            // 4p-16..4p-13; need those consumed: cons >= 4p+4-RS
            const int lim = 4 * p + 4 - RS;
            if (lim > 0) { while (*vcons < lim) {} }

            // stage 4 x rows (thread e loads one float per row — coalesced)
#pragma unroll
            for (int u = 0; u < 4; u++)
                xs[u][e] = __ldcs(&xsrc[(size_t)(4 * p + u) * XSTR + e]);
            PROD_BAR();   // xs visible to both producer warps

#pragma unroll
            for (int u = 0; u < 4; u++) {
                const int t = 4 * p + u;
                float3 d = dot64x3(wr, wz, wn, xs[u], br, bz, bn);
                float* slot = xq[t & (RS - 1)];
                slot[e]       = d.x;
                slot[64 + e]  = d.y;
                slot[128 + e] = d.z;
            }
            __threadfence_block();
            PROD_BAR();   // all producer writes done (incl. xs WAR for next grp)
            if (e == 0) *vprod = 4 * p + 4;
        }
        return;   // producers retire
    }

    // ============================== SCAN ==============================
    const int e = tid;   // 0..63
    ulonglong2 wr[16], wz[16], wn[16];
    {
        const ulonglong2* p;
        p = (const ulonglong2*)&Whh[((size_t)g * 192 + e) * Hn];
#pragma unroll
        for (int q = 0; q < 16; q++) wr[q] = p[q];
        p = (const ulonglong2*)&Whh[((size_t)g * 192 + 64 + e) * Hn];
#pragma unroll
        for (int q = 0; q < 16; q++) wz[q] = p[q];
        p = (const ulonglong2*)&Whh[((size_t)g * 192 + 128 + e) * Hn];
#pragma unroll
        for (int q = 0; q < 16; q++) wn[q] = p[q];
    }
    const float br = bhh[g * 192 + e];
    const float bz = bhh[g * 192 + 64 + e];
    const float bn = bhh[g * 192 + 128 + e];

    float hreg = h0[((size_t)g * Bn + b) * Hn + e];
    hbuf[0][e] = hreg;
    float* outp = out + (size_t)b * Tn * (Gn * Hn) + g * Hn + e;

    SCAN_BAR();   // hbuf[0] visible to both scan warps

    for (int t = 0; t < Tn; t++) {
        if ((t & 3) == 0) {
            // all reads of steps < t completed (bar at end of t-1 passed)
            if (e == 0) *vcons = t;
            const int need = (t + 4 < Tn) ? (t + 4) : Tn;
            while (*vprod < need) {}
            __threadfence_block();
        }

        float3 d = dot64x3(wr, wz, wn, hbuf[t & 1], br, bz, bn);

        const float* slot = xq[t & (RS - 1)];
        float rr = fsig(slot[e]       + d.x);
        float zz = fsig(slot[64 + e]  + d.y);
        float aa = slot[128 + e] + rr * d.z;
        float nn = __fmaf_rn(2.f, fsig(2.f * aa), -1.f);
        float hn = nn + zz * (hreg - nn);
        hreg = hn;
        hbuf[(t + 1) & 1][e] = hn;
        __stcs(&outp[(size_t)t * (Gn * Hn)], hn);

        SCAN_BAR();   // orders h write (t) before h read (t+1); xq reads done
    }

    // final hidden state
    out[(size_t)Bn * Tn * (Gn * Hn) + ((size_t)g * Bn + b) * Hn + e] = hreg;
}

// ---------------------------------------------------------------------------
extern "C" void kernel_launch(void* const* d_in, const int* in_sizes, int n_in,
                              void* d_out, int out_size)
{
    const float* x   = (const float*)d_in[0];
    const float* h0  = (const float*)d_in[1];
    const float* Wih = (const float*)d_in[2];
    const float* Whh = (const float*)d_in[3];
    const float* bih = (const float*)d_in[4];
    const float* bhh = (const float*)d_in[5];
    float* out = (float*)d_out;

    gru_kernel<<<Bn * Gn, 128>>>(x, h0, Wih, Whh, bih, bhh, out);
}